// round 15
// baseline (speedup 1.0000x reference)
#include <cuda_runtime.h>
#include <cuda_bf16.h>
#include <math.h>

// Problem constants (fixed by the dataset)
#define NN 8192      // nodes
#define EE 24576     // edges
#define DD 4         // node feature dim
#define HH 100       // hidden units

// ---------------------------------------------------------------------------
// Device scratch (no allocations allowed in kernel_launch)
// ---------------------------------------------------------------------------
__device__ unsigned int g_tag[EE];     // per-edge rendezvous: 0 = empty, else idx+1
__device__ float g_mi[NN * DD];
__device__ float g_mo[NN * DD];

// ---------------------------------------------------------------------------
// Kernel 1: scan the dense one-hot incidence matrices AND scatter inline.
//
// Each column of Ri/Ro [N, E] (row-major) has exactly one 1.0; over a row
// chunk compute fidx = sum_r r*M[r,c], found = sum_r M[r,c]. The unique chunk
// holding the 1.0 knows the index. Per edge there are exactly TWO finders
// (one in a z=0 block -> idx_i, one in a z=1 block -> idx_o). They rendezvous
// via atomicExch on g_tag[k]: first arriver deposits its index (+1); second
// arriver receives the other index in the exchange return value (the value
// travels through the atomic -> no fence needed) and performs the scatter:
//   mi[idx_i] += e[k] * X[idx_o] ;  mo[idx_o] += e[k] * X[idx_i]
//
// This kernel is the HBM roofline: 2 * N * E * 4B = 1.61 GB streamed once.
// Scan converged at ~7.25 TB/s (BATCH 8, 4 blocks/SM). R15: ROWS_PER_CHUNK
// 128 -> 256 halves the number of block prologue/epilogue queue drains.
// ---------------------------------------------------------------------------
#define SCAN_THREADS     256
#define COLS_PER_BLOCK   (SCAN_THREADS * 4)      // 1024
#define ROW_CHUNKS       32
#define ROWS_PER_CHUNK   (NN / ROW_CHUNKS)       // 256
#define BATCH            8

__device__ __forceinline__ void rendezvous_scatter(
    int c, float fidx, float found, int z,
    const float* __restrict__ X, const float* __restrict__ e)
{
    if (found == 0.f) return;
    int my = (int)fidx;
    unsigned old = atomicExch(&g_tag[c], (unsigned)(my + 1));
    if (old == 0u) return;            // first arriver: just deposited
    int other = (int)old - 1;
    int ii = (z == 0) ? my    : other;
    int io = (z == 0) ? other : my;

    float ek = e[c];
    float4 xo = reinterpret_cast<const float4*>(X)[io];
    float4 xi = reinterpret_cast<const float4*>(X)[ii];

    float* mi = g_mi + 4 * ii;
    atomicAdd(mi + 0, ek * xo.x);
    atomicAdd(mi + 1, ek * xo.y);
    atomicAdd(mi + 2, ek * xo.z);
    atomicAdd(mi + 3, ek * xo.w);

    float* mo = g_mo + 4 * io;
    atomicAdd(mo + 0, ek * xi.x);
    atomicAdd(mo + 1, ek * xi.y);
    atomicAdd(mo + 2, ek * xi.z);
    atomicAdd(mo + 3, ek * xi.w);
}

__global__ __launch_bounds__(SCAN_THREADS, 4)
void find_scatter_kernel(const float* __restrict__ Ri,
                         const float* __restrict__ Ro,
                         const float* __restrict__ X,
                         const float* __restrict__ e) {
    // --- prologue: zero accumulators + rendezvous tags (wave-1 blocks).
    //     z==0, y<8: 24*8 blocks * 256 thr = 49152 slots >= NN*DD and >= EE.
    if (blockIdx.z == 0 && blockIdx.y < 8) {
        int t = (blockIdx.y * gridDim.x + blockIdx.x) * SCAN_THREADS + threadIdx.x;
        if (t < NN * DD) { g_mi[t] = 0.0f; g_mo[t] = 0.0f; }
        if (t < EE)      g_tag[t] = 0u;
    }

    const int z = blockIdx.z;
    const float* M = (z == 0) ? Ri : Ro;

    const int col = blockIdx.x * COLS_PER_BLOCK + threadIdx.x * 4;
    const int r0  = blockIdx.y * ROWS_PER_CHUNK;

    const float4* p = reinterpret_cast<const float4*>(M + (long)r0 * EE + col);
    const int row_stride4 = EE / 4;  // float4 elements per row

    float fi0 = 0.f, fi1 = 0.f, fi2 = 0.f, fi3 = 0.f;
    float ff0 = 0.f, ff1 = 0.f, ff2 = 0.f, ff3 = 0.f;

    for (int rb = 0; rb < ROWS_PER_CHUNK; rb += BATCH) {
        // front-batch BATCH independent LDG.128s (deep MLP)
        float4 v[BATCH];
        #pragma unroll
        for (int j = 0; j < BATCH; ++j)
            v[j] = __ldcs(p + (long)(rb + j) * row_stride4);   // streaming

        #pragma unroll
        for (int j = 0; j < BATCH; ++j) {
            float fr = (float)(r0 + rb + j);
            fi0 = fmaf(v[j].x, fr, fi0); ff0 += v[j].x;
            fi1 = fmaf(v[j].y, fr, fi1); ff1 += v[j].y;
            fi2 = fmaf(v[j].z, fr, fi2); ff2 += v[j].z;
            fi3 = fmaf(v[j].w, fr, fi3); ff3 += v[j].w;
        }
    }

    // --- epilogue: rendezvous + inline scatter (second arriver does work) ---
    rendezvous_scatter(col + 0, fi0, ff0, z, X, e);
    rendezvous_scatter(col + 1, fi1, ff1, z, X, e);
    rendezvous_scatter(col + 2, fi2, ff2, z, X, e);
    rendezvous_scatter(col + 3, fi3, ff3, z, X, e);
}

// ---------------------------------------------------------------------------
// Fast device math
// ---------------------------------------------------------------------------
__device__ __forceinline__ float fast_tanh(float x) {
    float y;
    asm("tanh.approx.f32 %0, %1;" : "=f"(y) : "f"(x));
    return y;
}

// ---------------------------------------------------------------------------
// Kernel 2: fused MLP  out = sigmoid( tanh([mi,mo,X] @ W1 + b1) @ W2 + b2 )
// Best measured config: register-resident weights, 4 nodes/warp (prologue
// amortized -- proven optimum vs 1 and 2), phase-1 independent FMA chains,
// phase-2 interleaved butterflies (shfl latencies pipelined).
// R15: 128-thread blocks (512 blocks) for finer SM packing at 79 regs.
// ---------------------------------------------------------------------------
#define MLP_THREADS 128
#define WARPS_PER_BLOCK (MLP_THREADS / 32)                  // 4
#define NODES_PER_WARP  4
#define NODES_PER_BLOCK (WARPS_PER_BLOCK * NODES_PER_WARP)  // 16

__global__ __launch_bounds__(MLP_THREADS)
void mlp_kernel(const float* __restrict__ X,
                const float* __restrict__ W1, const float* __restrict__ b1,
                const float* __restrict__ W2, const float* __restrict__ b2,
                float* __restrict__ out) {
    const int warp = threadIdx.x >> 5;
    const int lane = threadIdx.x & 31;
    const int n0   = (blockIdx.x * WARPS_PER_BLOCK + warp) * NODES_PER_WARP;

    // --- load this lane's weight columns into registers (coalesced) ---
    float w1r[4][3 * DD];
    float b1r[4], w2r[4];
    #pragma unroll
    for (int jj = 0; jj < 4; ++jj) {
        const int j = jj * 32 + lane;
        const bool ok = (j < HH);
        b1r[jj] = ok ? __ldg(b1 + j) : 0.0f;
        w2r[jj] = ok ? __ldg(W2 + j) : 0.0f;
        #pragma unroll
        for (int i = 0; i < 3 * DD; ++i)
            w1r[jj][i] = ok ? __ldg(W1 + i * HH + j) : 0.0f;
    }
    const float bias2 = __ldg(b2);

    // --- phase 1: per-node partial sums (4 independent chains) ---
    float acc[NODES_PER_WARP];
    #pragma unroll
    for (int nn = 0; nn < NODES_PER_WARP; ++nn) {
        const int n = n0 + nn;

        // node input vector (same addresses across warp -> broadcast loads)
        float in[3 * DD];
        float4 a = reinterpret_cast<const float4*>(g_mi)[n];
        float4 b = reinterpret_cast<const float4*>(g_mo)[n];
        float4 c = reinterpret_cast<const float4*>(X)[n];
        in[0] = a.x; in[1] = a.y; in[2]  = a.z; in[3]  = a.w;
        in[4] = b.x; in[5] = b.y; in[6]  = b.z; in[7]  = b.w;
        in[8] = c.x; in[9] = c.y; in[10] = c.z; in[11] = c.w;

        float s_acc = 0.0f;
        #pragma unroll
        for (int jj = 0; jj < 4; ++jj) {
            float s = b1r[jj];
            #pragma unroll
            for (int i = 0; i < 3 * DD; ++i)
                s = fmaf(in[i], w1r[jj][i], s);
            s_acc = fmaf(fast_tanh(s), w2r[jj], s_acc);  // zero-weight lanes add 0
        }
        acc[nn] = s_acc;
    }

    // --- phase 2: 4 interleaved butterflies (shfl latency pipelined) ---
    #pragma unroll
    for (int step = 16; step >= 1; step >>= 1) {
        #pragma unroll
        for (int nn = 0; nn < NODES_PER_WARP; ++nn)
            acc[nn] += __shfl_xor_sync(0xFFFFFFFFu, acc[nn], step);
    }

    if (lane == 0) {
        #pragma unroll
        for (int nn = 0; nn < NODES_PER_WARP; ++nn)
            out[n0 + nn] = 1.0f / (1.0f + __expf(-(acc[nn] + bias2)));
    }
}

// ---------------------------------------------------------------------------
// Launch
// Inputs (metadata order): X, e, Ri, Ro, W1, b1, W2, b2
// ---------------------------------------------------------------------------
extern "C" void kernel_launch(void* const* d_in, const int* in_sizes, int n_in,
                              void* d_out, int out_size) {
    const float* X  = (const float*)d_in[0];
    const float* e  = (const float*)d_in[1];
    const float* Ri = (const float*)d_in[2];
    const float* Ro = (const float*)d_in[3];
    const float* W1 = (const float*)d_in[4];
    const float* b1 = (const float*)d_in[5];
    const float* W2 = (const float*)d_in[6];
    const float* b2 = (const float*)d_in[7];
    float* out = (float*)d_out;

    // 1) scan Ri/Ro (HBM-bound) with inline rendezvous scatter + zeroing
    dim3 grid(EE / COLS_PER_BLOCK, ROW_CHUNKS, 2);   // (24, 32, 2) = 1536 blocks
    find_scatter_kernel<<<grid, SCAN_THREADS>>>(Ri, Ro, X, e);

    // 2) fused MLP: register weights, 4 nodes/warp, interleaved reduce
    mlp_kernel<<<NN / NODES_PER_BLOCK, MLP_THREADS>>>(X, W1, b1, W2, b2, out);
}

// round 16
// speedup vs baseline: 1.0007x; 1.0007x over previous
#include <cuda_runtime.h>
#include <cuda_bf16.h>
#include <math.h>

// Problem constants (fixed by the dataset)
#define NN 8192      // nodes
#define EE 24576     // edges
#define DD 4         // node feature dim
#define HH 100       // hidden units

// ---------------------------------------------------------------------------
// Device scratch (no allocations allowed in kernel_launch)
// ---------------------------------------------------------------------------
__device__ unsigned int g_tag[EE];     // per-edge rendezvous: 0 = empty, else idx+1
__device__ float g_mi[NN * DD];
__device__ float g_mo[NN * DD];

// ---------------------------------------------------------------------------
// Kernel 1: scan the dense one-hot incidence matrices AND scatter inline.
//
// Each column of Ri/Ro [N, E] (row-major) has exactly one 1.0; over a row
// chunk compute fidx = sum_r r*M[r,c], found = sum_r M[r,c]. The unique chunk
// holding the 1.0 knows the index. Per edge there are exactly TWO finders
// (one in a z=0 block -> idx_i, one in a z=1 block -> idx_o). They rendezvous
// via atomicExch on g_tag[k]: first arriver deposits its index (+1); second
// arriver receives the other index in the exchange return value (the value
// travels through the atomic -> no fence needed) and performs the scatter:
//   mi[idx_i] += e[k] * X[idx_o] ;  mo[idx_o] += e[k] * X[idx_i]
//
// This kernel is the HBM roofline: 2 * N * E * 4B = 1.61 GB streamed once.
// Converged at ~7.25 TB/s. Explored to neutrality/regression: BATCH 16,
// persistent grid-stride, ROWS_PER_CHUNK 256, occupancy 3/4 blocks-per-SM.
// ---------------------------------------------------------------------------
#define SCAN_THREADS     256
#define COLS_PER_BLOCK   (SCAN_THREADS * 4)      // 1024
#define ROW_CHUNKS       64
#define ROWS_PER_CHUNK   (NN / ROW_CHUNKS)       // 128
#define BATCH            8

__device__ __forceinline__ void rendezvous_scatter(
    int c, float fidx, float found, int z,
    const float* __restrict__ X, const float* __restrict__ e)
{
    if (found == 0.f) return;
    int my = (int)fidx;
    unsigned old = atomicExch(&g_tag[c], (unsigned)(my + 1));
    if (old == 0u) return;            // first arriver: just deposited
    int other = (int)old - 1;
    int ii = (z == 0) ? my    : other;
    int io = (z == 0) ? other : my;

    float ek = e[c];
    float4 xo = reinterpret_cast<const float4*>(X)[io];
    float4 xi = reinterpret_cast<const float4*>(X)[ii];

    float* mi = g_mi + 4 * ii;
    atomicAdd(mi + 0, ek * xo.x);
    atomicAdd(mi + 1, ek * xo.y);
    atomicAdd(mi + 2, ek * xo.z);
    atomicAdd(mi + 3, ek * xo.w);

    float* mo = g_mo + 4 * io;
    atomicAdd(mo + 0, ek * xi.x);
    atomicAdd(mo + 1, ek * xi.y);
    atomicAdd(mo + 2, ek * xi.z);
    atomicAdd(mo + 3, ek * xi.w);
}

__global__ __launch_bounds__(SCAN_THREADS, 4)
void find_scatter_kernel(const float* __restrict__ Ri,
                         const float* __restrict__ Ro,
                         const float* __restrict__ X,
                         const float* __restrict__ e) {
    // --- prologue: zero accumulators + rendezvous tags (wave-1 blocks).
    //     z==0, y<8: 24*8 blocks * 256 thr = 49152 slots >= NN*DD and >= EE.
    if (blockIdx.z == 0 && blockIdx.y < 8) {
        int t = (blockIdx.y * gridDim.x + blockIdx.x) * SCAN_THREADS + threadIdx.x;
        if (t < NN * DD) { g_mi[t] = 0.0f; g_mo[t] = 0.0f; }
        if (t < EE)      g_tag[t] = 0u;
    }

    const int z = blockIdx.z;
    const float* M = (z == 0) ? Ri : Ro;

    const int col = blockIdx.x * COLS_PER_BLOCK + threadIdx.x * 4;
    const int r0  = blockIdx.y * ROWS_PER_CHUNK;

    const float4* p = reinterpret_cast<const float4*>(M + (long)r0 * EE + col);
    const int row_stride4 = EE / 4;  // float4 elements per row

    float fi0 = 0.f, fi1 = 0.f, fi2 = 0.f, fi3 = 0.f;
    float ff0 = 0.f, ff1 = 0.f, ff2 = 0.f, ff3 = 0.f;

    for (int rb = 0; rb < ROWS_PER_CHUNK; rb += BATCH) {
        // front-batch BATCH independent LDG.128s (deep MLP)
        float4 v[BATCH];
        #pragma unroll
        for (int j = 0; j < BATCH; ++j)
            v[j] = __ldcs(p + (long)(rb + j) * row_stride4);   // streaming

        #pragma unroll
        for (int j = 0; j < BATCH; ++j) {
            float fr = (float)(r0 + rb + j);
            fi0 = fmaf(v[j].x, fr, fi0); ff0 += v[j].x;
            fi1 = fmaf(v[j].y, fr, fi1); ff1 += v[j].y;
            fi2 = fmaf(v[j].z, fr, fi2); ff2 += v[j].z;
            fi3 = fmaf(v[j].w, fr, fi3); ff3 += v[j].w;
        }
    }

    // --- epilogue: rendezvous + inline scatter (second arriver does work) ---
    rendezvous_scatter(col + 0, fi0, ff0, z, X, e);
    rendezvous_scatter(col + 1, fi1, ff1, z, X, e);
    rendezvous_scatter(col + 2, fi2, ff2, z, X, e);
    rendezvous_scatter(col + 3, fi3, ff3, z, X, e);
}

// ---------------------------------------------------------------------------
// Fast device math
// ---------------------------------------------------------------------------
__device__ __forceinline__ float fast_tanh(float x) {
    float y;
    asm("tanh.approx.f32 %0, %1;" : "=f"(y) : "f"(x));
    return y;
}

// ---------------------------------------------------------------------------
// Kernel 2: fused MLP  out = sigmoid( tanh([mi,mo,X] @ W1 + b1) @ W2 + b2 )
// Best measured config (6.46us): register-resident weights (node-invariant,
// coalesced L2-hit loads; no smem, no __syncthreads), 4 nodes/warp (prologue
// amortization optimum vs 1 and 2), phase-1 independent FMA chains, phase-2
// interleaved butterflies (four 5-step shfl reductions pipeline their 26-cyc
// latencies), 128-thread blocks for fine SM packing.
// ---------------------------------------------------------------------------
#define MLP_THREADS 128
#define WARPS_PER_BLOCK (MLP_THREADS / 32)                  // 4
#define NODES_PER_WARP  4
#define NODES_PER_BLOCK (WARPS_PER_BLOCK * NODES_PER_WARP)  // 16

__global__ __launch_bounds__(MLP_THREADS)
void mlp_kernel(const float* __restrict__ X,
                const float* __restrict__ W1, const float* __restrict__ b1,
                const float* __restrict__ W2, const float* __restrict__ b2,
                float* __restrict__ out) {
    const int warp = threadIdx.x >> 5;
    const int lane = threadIdx.x & 31;
    const int n0   = (blockIdx.x * WARPS_PER_BLOCK + warp) * NODES_PER_WARP;

    // --- load this lane's weight columns into registers (coalesced) ---
    float w1r[4][3 * DD];
    float b1r[4], w2r[4];
    #pragma unroll
    for (int jj = 0; jj < 4; ++jj) {
        const int j = jj * 32 + lane;
        const bool ok = (j < HH);
        b1r[jj] = ok ? __ldg(b1 + j) : 0.0f;
        w2r[jj] = ok ? __ldg(W2 + j) : 0.0f;
        #pragma unroll
        for (int i = 0; i < 3 * DD; ++i)
            w1r[jj][i] = ok ? __ldg(W1 + i * HH + j) : 0.0f;
    }
    const float bias2 = __ldg(b2);

    // --- phase 1: per-node partial sums (4 independent chains) ---
    float acc[NODES_PER_WARP];
    #pragma unroll
    for (int nn = 0; nn < NODES_PER_WARP; ++nn) {
        const int n = n0 + nn;

        // node input vector (same addresses across warp -> broadcast loads)
        float in[3 * DD];
        float4 a = reinterpret_cast<const float4*>(g_mi)[n];
        float4 b = reinterpret_cast<const float4*>(g_mo)[n];
        float4 c = reinterpret_cast<const float4*>(X)[n];
        in[0] = a.x; in[1] = a.y; in[2]  = a.z; in[3]  = a.w;
        in[4] = b.x; in[5] = b.y; in[6]  = b.z; in[7]  = b.w;
        in[8] = c.x; in[9] = c.y; in[10] = c.z; in[11] = c.w;

        float s_acc = 0.0f;
        #pragma unroll
        for (int jj = 0; jj < 4; ++jj) {
            float s = b1r[jj];
            #pragma unroll
            for (int i = 0; i < 3 * DD; ++i)
                s = fmaf(in[i], w1r[jj][i], s);
            s_acc = fmaf(fast_tanh(s), w2r[jj], s_acc);  // zero-weight lanes add 0
        }
        acc[nn] = s_acc;
    }

    // --- phase 2: 4 interleaved butterflies (shfl latency pipelined) ---
    #pragma unroll
    for (int step = 16; step >= 1; step >>= 1) {
        #pragma unroll
        for (int nn = 0; nn < NODES_PER_WARP; ++nn)
            acc[nn] += __shfl_xor_sync(0xFFFFFFFFu, acc[nn], step);
    }

    if (lane == 0) {
        #pragma unroll
        for (int nn = 0; nn < NODES_PER_WARP; ++nn)
            out[n0 + nn] = 1.0f / (1.0f + __expf(-(acc[nn] + bias2)));
    }
}

// ---------------------------------------------------------------------------
// Launch
// Inputs (metadata order): X, e, Ri, Ro, W1, b1, W2, b2
// ---------------------------------------------------------------------------
extern "C" void kernel_launch(void* const* d_in, const int* in_sizes, int n_in,
                              void* d_out, int out_size) {
    const float* X  = (const float*)d_in[0];
    const float* e  = (const float*)d_in[1];
    const float* Ri = (const float*)d_in[2];
    const float* Ro = (const float*)d_in[3];
    const float* W1 = (const float*)d_in[4];
    const float* b1 = (const float*)d_in[5];
    const float* W2 = (const float*)d_in[6];
    const float* b2 = (const float*)d_in[7];
    float* out = (float*)d_out;

    // 1) scan Ri/Ro (HBM-bound) with inline rendezvous scatter + zeroing
    dim3 grid(EE / COLS_PER_BLOCK, ROW_CHUNKS, 2);   // (24, 64, 2) = 3072 blocks
    find_scatter_kernel<<<grid, SCAN_THREADS>>>(Ri, Ro, X, e);

    // 2) fused MLP: register weights, 4 nodes/warp, interleaved reduce
    mlp_kernel<<<NN / NODES_PER_BLOCK, MLP_THREADS>>>(X, W1, b1, W2, b2, out);
}

// round 17
// speedup vs baseline: 1.0164x; 1.0157x over previous
#include <cuda_runtime.h>
#include <cuda_bf16.h>
#include <math.h>

// Problem constants (fixed by the dataset)
#define NN 8192      // nodes
#define EE 24576     // edges
#define DD 4         // node feature dim
#define HH 100       // hidden units

// ---------------------------------------------------------------------------
// Device scratch (no allocations allowed in kernel_launch)
// ---------------------------------------------------------------------------
__device__ unsigned int g_tag[EE];     // per-edge rendezvous: 0 = empty, else idx+1
__device__ float g_mi[NN * DD];
__device__ float g_mo[NN * DD];

// ---------------------------------------------------------------------------
// Kernel 1: scan the dense one-hot incidence matrices AND scatter inline.
//
// Each column of Ri/Ro [N, E] (row-major) has exactly one 1.0; over a row
// chunk compute fidx = sum_r r*M[r,c], found = sum_r M[r,c]. The unique chunk
// holding the 1.0 knows the index. Per edge there are exactly TWO finders
// (one in a z=0 block -> idx_i, one in a z=1 block -> idx_o). They rendezvous
// via atomicExch on g_tag[k]: first arriver deposits its index (+1); second
// arriver receives the other index in the exchange return value (the value
// travels through the atomic -> no fence needed) and performs the scatter:
//   mi[idx_i] += e[k] * X[idx_o] ;  mo[idx_o] += e[k] * X[idx_i]
//
// This kernel is the HBM roofline: 2 * N * E * 4B = 1.61 GB streamed once.
// Converged at ~7.25 TB/s. Explored to neutrality/regression: BATCH 16,
// persistent grid-stride, ROWS_PER_CHUNK 256, occupancy 3/4 blocks-per-SM.
// ---------------------------------------------------------------------------
#define SCAN_THREADS     256
#define COLS_PER_BLOCK   (SCAN_THREADS * 4)      // 1024
#define ROW_CHUNKS       64
#define ROWS_PER_CHUNK   (NN / ROW_CHUNKS)       // 128
#define BATCH            8

__device__ __forceinline__ void rendezvous_scatter(
    int c, float fidx, float found, int z,
    const float* __restrict__ X, const float* __restrict__ e)
{
    if (found == 0.f) return;
    int my = (int)fidx;
    unsigned old = atomicExch(&g_tag[c], (unsigned)(my + 1));
    if (old == 0u) return;            // first arriver: just deposited
    int other = (int)old - 1;
    int ii = (z == 0) ? my    : other;
    int io = (z == 0) ? other : my;

    float ek = e[c];
    float4 xo = reinterpret_cast<const float4*>(X)[io];
    float4 xi = reinterpret_cast<const float4*>(X)[ii];

    float* mi = g_mi + 4 * ii;
    atomicAdd(mi + 0, ek * xo.x);
    atomicAdd(mi + 1, ek * xo.y);
    atomicAdd(mi + 2, ek * xo.z);
    atomicAdd(mi + 3, ek * xo.w);

    float* mo = g_mo + 4 * io;
    atomicAdd(mo + 0, ek * xi.x);
    atomicAdd(mo + 1, ek * xi.y);
    atomicAdd(mo + 2, ek * xi.z);
    atomicAdd(mo + 3, ek * xi.w);
}

__global__ __launch_bounds__(SCAN_THREADS, 4)
void find_scatter_kernel(const float* __restrict__ Ri,
                         const float* __restrict__ Ro,
                         const float* __restrict__ X,
                         const float* __restrict__ e) {
    // --- prologue: zero accumulators + rendezvous tags (wave-1 blocks).
    //     z==0, y<8: 24*8 blocks * 256 thr = 49152 slots >= NN*DD and >= EE.
    if (blockIdx.z == 0 && blockIdx.y < 8) {
        int t = (blockIdx.y * gridDim.x + blockIdx.x) * SCAN_THREADS + threadIdx.x;
        if (t < NN * DD) { g_mi[t] = 0.0f; g_mo[t] = 0.0f; }
        if (t < EE)      g_tag[t] = 0u;
    }

    const int z = blockIdx.z;
    const float* M = (z == 0) ? Ri : Ro;

    const int col = blockIdx.x * COLS_PER_BLOCK + threadIdx.x * 4;
    const int r0  = blockIdx.y * ROWS_PER_CHUNK;

    const float4* p = reinterpret_cast<const float4*>(M + (long)r0 * EE + col);
    const int row_stride4 = EE / 4;  // float4 elements per row

    float fi0 = 0.f, fi1 = 0.f, fi2 = 0.f, fi3 = 0.f;
    float ff0 = 0.f, ff1 = 0.f, ff2 = 0.f, ff3 = 0.f;

    for (int rb = 0; rb < ROWS_PER_CHUNK; rb += BATCH) {
        // front-batch BATCH independent LDG.128s (deep MLP)
        float4 v[BATCH];
        #pragma unroll
        for (int j = 0; j < BATCH; ++j)
            v[j] = __ldcs(p + (long)(rb + j) * row_stride4);   // streaming

        #pragma unroll
        for (int j = 0; j < BATCH; ++j) {
            float fr = (float)(r0 + rb + j);
            fi0 = fmaf(v[j].x, fr, fi0); ff0 += v[j].x;
            fi1 = fmaf(v[j].y, fr, fi1); ff1 += v[j].y;
            fi2 = fmaf(v[j].z, fr, fi2); ff2 += v[j].z;
            fi3 = fmaf(v[j].w, fr, fi3); ff3 += v[j].w;
        }
    }

    // --- epilogue: rendezvous + inline scatter (second arriver does work) ---
    rendezvous_scatter(col + 0, fi0, ff0, z, X, e);
    rendezvous_scatter(col + 1, fi1, ff1, z, X, e);
    rendezvous_scatter(col + 2, fi2, ff2, z, X, e);
    rendezvous_scatter(col + 3, fi3, ff3, z, X, e);
}

// ---------------------------------------------------------------------------
// Fast device math
// ---------------------------------------------------------------------------
__device__ __forceinline__ float fast_tanh(float x) {
    float y;
    asm("tanh.approx.f32 %0, %1;" : "=f"(y) : "f"(x));
    return y;
}

// ---------------------------------------------------------------------------
// Kernel 2: fused MLP  out = sigmoid( tanh([mi,mo,X] @ W1 + b1) @ W2 + b2 )
// R17: launched with PROGRAMMATIC dependent launch. The scan-independent
// prologue (weight loads into registers) runs while find_scatter is still
// executing; cudaGridDependencySynchronize() then blocks until the scan
// (and its scatter atomics) fully completes before g_mi/g_mo are read.
// Config otherwise = best measured: register weights, 4 nodes/warp,
// interleaved butterflies, 128-thread blocks.
// ---------------------------------------------------------------------------
#define MLP_THREADS 128
#define WARPS_PER_BLOCK (MLP_THREADS / 32)                  // 4
#define NODES_PER_WARP  4
#define NODES_PER_BLOCK (WARPS_PER_BLOCK * NODES_PER_WARP)  // 16

__global__ __launch_bounds__(MLP_THREADS)
void mlp_kernel(const float* __restrict__ X,
                const float* __restrict__ W1, const float* __restrict__ b1,
                const float* __restrict__ W2, const float* __restrict__ b2,
                float* __restrict__ out) {
    const int warp = threadIdx.x >> 5;
    const int lane = threadIdx.x & 31;
    const int n0   = (blockIdx.x * WARPS_PER_BLOCK + warp) * NODES_PER_WARP;

    // --- scan-independent prologue: lane's weight columns into registers ---
    float w1r[4][3 * DD];
    float b1r[4], w2r[4];
    #pragma unroll
    for (int jj = 0; jj < 4; ++jj) {
        const int j = jj * 32 + lane;
        const bool ok = (j < HH);
        b1r[jj] = ok ? __ldg(b1 + j) : 0.0f;
        w2r[jj] = ok ? __ldg(W2 + j) : 0.0f;
        #pragma unroll
        for (int i = 0; i < 3 * DD; ++i)
            w1r[jj][i] = ok ? __ldg(W1 + i * HH + j) : 0.0f;
    }
    const float bias2 = __ldg(b2);

    // --- wait for find_scatter_kernel (scatter atomics included) ---
    cudaGridDependencySynchronize();

    // --- phase 1: per-node partial sums (4 independent chains) ---
    float acc[NODES_PER_WARP];
    #pragma unroll
    for (int nn = 0; nn < NODES_PER_WARP; ++nn) {
        const int n = n0 + nn;

        // node input vector (same addresses across warp -> broadcast loads)
        float in[3 * DD];
        float4 a = reinterpret_cast<const float4*>(g_mi)[n];
        float4 b = reinterpret_cast<const float4*>(g_mo)[n];
        float4 c = reinterpret_cast<const float4*>(X)[n];
        in[0] = a.x; in[1] = a.y; in[2]  = a.z; in[3]  = a.w;
        in[4] = b.x; in[5] = b.y; in[6]  = b.z; in[7]  = b.w;
        in[8] = c.x; in[9] = c.y; in[10] = c.z; in[11] = c.w;

        float s_acc = 0.0f;
        #pragma unroll
        for (int jj = 0; jj < 4; ++jj) {
            float s = b1r[jj];
            #pragma unroll
            for (int i = 0; i < 3 * DD; ++i)
                s = fmaf(in[i], w1r[jj][i], s);
            s_acc = fmaf(fast_tanh(s), w2r[jj], s_acc);  // zero-weight lanes add 0
        }
        acc[nn] = s_acc;
    }

    // --- phase 2: 4 interleaved butterflies (shfl latency pipelined) ---
    #pragma unroll
    for (int step = 16; step >= 1; step >>= 1) {
        #pragma unroll
        for (int nn = 0; nn < NODES_PER_WARP; ++nn)
            acc[nn] += __shfl_xor_sync(0xFFFFFFFFu, acc[nn], step);
    }

    if (lane == 0) {
        #pragma unroll
        for (int nn = 0; nn < NODES_PER_WARP; ++nn)
            out[n0 + nn] = 1.0f / (1.0f + __expf(-(acc[nn] + bias2)));
    }
}

// ---------------------------------------------------------------------------
// Launch
// Inputs (metadata order): X, e, Ri, Ro, W1, b1, W2, b2
// ---------------------------------------------------------------------------
extern "C" void kernel_launch(void* const* d_in, const int* in_sizes, int n_in,
                              void* d_out, int out_size) {
    const float* X  = (const float*)d_in[0];
    const float* e  = (const float*)d_in[1];
    const float* Ri = (const float*)d_in[2];
    const float* Ro = (const float*)d_in[3];
    const float* W1 = (const float*)d_in[4];
    const float* b1 = (const float*)d_in[5];
    const float* W2 = (const float*)d_in[6];
    const float* b2 = (const float*)d_in[7];
    float* out = (float*)d_out;

    // 1) scan Ri/Ro (HBM-bound) with inline rendezvous scatter + zeroing
    dim3 grid(EE / COLS_PER_BLOCK, ROW_CHUNKS, 2);   // (24, 64, 2) = 3072 blocks
    find_scatter_kernel<<<grid, SCAN_THREADS>>>(Ri, Ro, X, e);

    // 2) fused MLP via programmatic dependent launch: weight prologue
    //    overlaps the scan tail; grid-dependency sync guards g_mi/g_mo reads.
    {
        cudaLaunchConfig_t cfg = {};
        cfg.gridDim  = dim3(NN / NODES_PER_BLOCK);   // 512 blocks
        cfg.blockDim = dim3(MLP_THREADS);
        cfg.dynamicSmemBytes = 0;
        cfg.stream = 0;                              // same (default) stream
        cudaLaunchAttribute attrs[1];
        attrs[0].id = cudaLaunchAttributeProgrammaticStreamSerialization;
        attrs[0].val.programmaticStreamSerializationAllowed = 1;
        cfg.attrs = attrs;
        cfg.numAttrs = 1;
        cudaLaunchKernelEx(&cfg, mlp_kernel, X, W1, b1, W2, b2, out);
    }
}